// round 1
// baseline (speedup 1.0000x reference)
#include <cuda_runtime.h>
#include <cstdint>
#include <cstddef>

// Problem constants (fixed by the dataset)
#define BB 16
#define MM 16
#define JXN 128
#define JQN 64
#define DN 256

// Scratch for per-row max(s over q) + s_h  (p-softmax input), B*M*JX floats
__device__ float g_rowmax[BB * MM * JXN];

// shared memory layout strides (floats)
constexpr int UT_S  = 68;   // u_t  [256][68]  (u transposed: [d][q])
constexpr int USM_S = 260;  // u_sm [64][260]  (u row-major:  [q][d])
constexpr int AS_S  = 36;   // A_s  [64][36]   (h*w3 chunk, row-major, k-chunk=32)
constexpr int AT_S  = 68;   // a_t  [64][68]   (softmaxed attention transposed [q][row])

constexpr int SMEM_FLOATS = 256*UT_S + 64*USM_S + 64*AS_S + 64*AT_S + 3*DN + 64 + 64;

// ---------------------------------------------------------------------------
// Kernel 1: per CTA = one (b,m) pair, one 64-row half of JX.
//  - GEMM1: C[j,q] = sum_d (h[j,d]*w3[d]) * u[q,d]           (64x64x256)
//  - softmax over q of (C + s_u)  -> a_t ;  rowmax+s_h -> scratch
//  - GEMM2: u_att[j,d] = sum_q a[j,q]*u[q,d]                 (64x256x64)
//  - writes out segments: [0:D)=h, [D:2D)=u_att, [2D:3D)=h*u_att
// ---------------------------------------------------------------------------
__global__ void __launch_bounds__(256, 1)
attn_k1(const float* __restrict__ hg, const float* __restrict__ ug,
        const float* __restrict__ wg, float* __restrict__ out)
{
    extern __shared__ float sm[];
    float* u_t  = sm;                     // 256*68
    float* u_sm = u_t  + 256 * UT_S;      // 64*260
    float* A_s  = u_sm + 64  * USM_S;     // 64*36
    float* a_t  = A_s  + 64  * AS_S;      // 64*68
    float* w_s  = a_t  + 64  * AT_S;      // 768  (w1|w2|w3)
    float* s_u  = w_s  + 3 * DN;          // 64
    float* s_h  = s_u  + 64;              // 64

    const int tid = threadIdx.x;
    const int bm  = blockIdx.x >> 1;
    const int j0  = (blockIdx.x & 1) * 64;
    const int b   = bm >> 4;

    const float* __restrict__ hrow = hg + (size_t)(bm * JXN + j0) * DN;
    const float* __restrict__ ub   = ug + (size_t)b * JQN * DN;

    // ---- load w into smem ----
    for (int i = tid; i < 3 * DN; i += 256) w_s[i] = wg[i];

    // ---- fill u_sm (row-major copy of u[b], coalesced) ----
    for (int idx = tid; idx < JQN * (DN / 4); idx += 256) {
        int q = idx >> 6, d4 = idx & 63;
        float4 v = *(const float4*)(ub + q * DN + d4 * 4);
        *(float4*)(u_sm + q * USM_S + d4 * 4) = v;
    }
    // ---- fill u_t (transposed [d][q]; smem-store conflict-free mapping) ----
    for (int idx = tid; idx < (DN / 4) * JQN; idx += 256) {
        int d4 = idx >> 6, q = idx & 63;
        float4 v = *(const float4*)(ub + q * DN + d4 * 4);
        u_t[(d4 * 4 + 0) * UT_S + q] = v.x;
        u_t[(d4 * 4 + 1) * UT_S + q] = v.y;
        u_t[(d4 * 4 + 2) * UT_S + q] = v.z;
        u_t[(d4 * 4 + 3) * UT_S + q] = v.w;
    }
    __syncthreads();

    // ---- s_u[q] = u[q,:] . w2  (conflict-free via u_t) ----
    if (tid < 64) {
        float acc = 0.f;
        #pragma unroll 8
        for (int k = 0; k < DN; k++) acc += u_t[k * UT_S + tid] * w_s[DN + k];
        s_u[tid] = acc;
    }

    const int ty = tid >> 4, tx = tid & 15;   // thread tile: rows 4*ty.., q 4*tx..
    const int row_a = tid >> 3;               // staging: rows row_a, row_a+32
    const int k4a   = (tid & 7) * 4;          // staging: 4 k's within chunk

    float c1[4][4];
    #pragma unroll
    for (int r = 0; r < 4; r++)
        #pragma unroll
        for (int j = 0; j < 4; j++) c1[r][j] = 0.f;

    float sh0 = 0.f, sh1 = 0.f;   // partial h.w1 for rows row_a, row_a+32

    // prefetch chunk 0 of A (h rows) into registers
    float4 pa0 = *(const float4*)(hrow + row_a * DN + k4a);
    float4 pa1 = *(const float4*)(hrow + (row_a + 32) * DN + k4a);

    // ---- GEMM1 main loop: 8 k-chunks of 32 ----
    for (int c = 0; c < 8; c++) {
        const int kc = c * 32;
        // s_h partials (w1) computed from raw h
        sh0 += pa0.x * w_s[kc + k4a + 0] + pa0.y * w_s[kc + k4a + 1]
             + pa0.z * w_s[kc + k4a + 2] + pa0.w * w_s[kc + k4a + 3];
        sh1 += pa1.x * w_s[kc + k4a + 0] + pa1.y * w_s[kc + k4a + 1]
             + pa1.z * w_s[kc + k4a + 2] + pa1.w * w_s[kc + k4a + 3];
        // scale by w3 and stage to smem
        const float* w3 = w_s + 2 * DN + kc + k4a;
        float4 t0, t1;
        t0.x = pa0.x * w3[0]; t0.y = pa0.y * w3[1]; t0.z = pa0.z * w3[2]; t0.w = pa0.w * w3[3];
        t1.x = pa1.x * w3[0]; t1.y = pa1.y * w3[1]; t1.z = pa1.z * w3[2]; t1.w = pa1.w * w3[3];
        *(float4*)(A_s + row_a * AS_S + k4a)        = t0;
        *(float4*)(A_s + (row_a + 32) * AS_S + k4a) = t1;
        __syncthreads();
        // prefetch next chunk (hides LDG latency under compute)
        if (c < 7) {
            pa0 = *(const float4*)(hrow + row_a * DN + kc + 32 + k4a);
            pa1 = *(const float4*)(hrow + (row_a + 32) * DN + kc + 32 + k4a);
        }
        // register-tiled 4x4 FMA over this k-chunk
        #pragma unroll 8
        for (int kk = 0; kk < 32; kk++) {
            float a0 = A_s[(ty * 4 + 0) * AS_S + kk];
            float a1 = A_s[(ty * 4 + 1) * AS_S + kk];
            float a2 = A_s[(ty * 4 + 2) * AS_S + kk];
            float a3 = A_s[(ty * 4 + 3) * AS_S + kk];
            float4 bb = *(const float4*)(u_t + (kc + kk) * UT_S + tx * 4);
            c1[0][0] += a0 * bb.x; c1[0][1] += a0 * bb.y; c1[0][2] += a0 * bb.z; c1[0][3] += a0 * bb.w;
            c1[1][0] += a1 * bb.x; c1[1][1] += a1 * bb.y; c1[1][2] += a1 * bb.z; c1[1][3] += a1 * bb.w;
            c1[2][0] += a2 * bb.x; c1[2][1] += a2 * bb.y; c1[2][2] += a2 * bb.z; c1[2][3] += a2 * bb.w;
            c1[3][0] += a3 * bb.x; c1[3][1] += a3 * bb.y; c1[3][2] += a3 * bb.z; c1[3][3] += a3 * bb.w;
        }
        __syncthreads();
    }

    // ---- reduce s_h partials over the 8 lanes sharing a row ----
    #pragma unroll
    for (int o = 4; o >= 1; o >>= 1) {
        sh0 += __shfl_down_sync(0xffffffffu, sh0, o, 8);
        sh1 += __shfl_down_sync(0xffffffffu, sh1, o, 8);
    }
    if ((tid & 7) == 0) { s_h[row_a] = sh0; s_h[row_a + 32] = sh1; }
    __syncthreads();

    // ---- epilogue: softmax over q (s_h and bias cancel), write a_t + rowmax ----
    #pragma unroll
    for (int r = 0; r < 4; r++) {
        const int row = ty * 4 + r;
        float v0 = c1[r][0] + s_u[tx * 4 + 0];
        float v1 = c1[r][1] + s_u[tx * 4 + 1];
        float v2 = c1[r][2] + s_u[tx * 4 + 2];
        float v3 = c1[r][3] + s_u[tx * 4 + 3];
        float mx = fmaxf(fmaxf(v0, v1), fmaxf(v2, v3));
        #pragma unroll
        for (int o = 8; o >= 1; o >>= 1) mx = fmaxf(mx, __shfl_xor_sync(0xffffffffu, mx, o, 16));
        float e0 = __expf(v0 - mx), e1 = __expf(v1 - mx);
        float e2 = __expf(v2 - mx), e3 = __expf(v3 - mx);
        float sum = e0 + e1 + e2 + e3;
        #pragma unroll
        for (int o = 8; o >= 1; o >>= 1) sum += __shfl_xor_sync(0xffffffffu, sum, o, 16);
        float inv = 1.f / sum;
        a_t[(tx * 4 + 0) * AT_S + row] = e0 * inv;
        a_t[(tx * 4 + 1) * AT_S + row] = e1 * inv;
        a_t[(tx * 4 + 2) * AT_S + row] = e2 * inv;
        a_t[(tx * 4 + 3) * AT_S + row] = e3 * inv;
        if (tx == 0) g_rowmax[bm * JXN + j0 + row] = mx + s_h[row];
    }
    __syncthreads();

    // ---- GEMM2 (u_att) + write segments 0..2 ----
    const size_t outbase = (size_t)(bm * JXN + j0) * (4 * DN);
    for (int p = 0; p < 4; p++) {
        float c2[4][4];
        #pragma unroll
        for (int r = 0; r < 4; r++)
            #pragma unroll
            for (int j = 0; j < 4; j++) c2[r][j] = 0.f;
        #pragma unroll 8
        for (int k = 0; k < 64; k++) {
            float4 aa = *(const float4*)(a_t + k * AT_S + ty * 4);
            float4 bb = *(const float4*)(u_sm + k * USM_S + p * 64 + tx * 4);
            c2[0][0] += aa.x * bb.x; c2[0][1] += aa.x * bb.y; c2[0][2] += aa.x * bb.z; c2[0][3] += aa.x * bb.w;
            c2[1][0] += aa.y * bb.x; c2[1][1] += aa.y * bb.y; c2[1][2] += aa.y * bb.z; c2[1][3] += aa.y * bb.w;
            c2[2][0] += aa.z * bb.x; c2[2][1] += aa.z * bb.y; c2[2][2] += aa.z * bb.z; c2[2][3] += aa.z * bb.w;
            c2[3][0] += aa.w * bb.x; c2[3][1] += aa.w * bb.y; c2[3][2] += aa.w * bb.z; c2[3][3] += aa.w * bb.w;
        }
        #pragma unroll
        for (int r = 0; r < 4; r++) {
            const int row = ty * 4 + r;
            const int dg  = p * 64 + tx * 4;
            float4 h4 = *(const float4*)(hrow + row * DN + dg);   // L2-hot reload
            float4 ua = make_float4(c2[r][0], c2[r][1], c2[r][2], c2[r][3]);
            float4 hu = make_float4(h4.x * ua.x, h4.y * ua.y, h4.z * ua.z, h4.w * ua.w);
            float* ob = out + outbase + (size_t)row * (4 * DN);
            *(float4*)(ob + dg)           = h4;   // segment 0: h
            *(float4*)(ob + DN + dg)      = ua;   // segment 1: u_att
            *(float4*)(ob + 2 * DN + dg)  = hu;   // segment 2: h*u_att
        }
    }
}

// ---------------------------------------------------------------------------
// Kernel 2: per CTA = one (b,m). p = softmax_j(rowmax); h_att = sum_j p_j h_j;
// writes segment 3: h * h_att (broadcast over j).
// ---------------------------------------------------------------------------
__global__ void __launch_bounds__(256)
attn_k2(const float* __restrict__ hg, float* __restrict__ out)
{
    __shared__ float  p_s[JXN];
    __shared__ float4 part[4][64];

    const int bm  = blockIdx.x;
    const int tid = threadIdx.x;
    const float* __restrict__ hb = hg + (size_t)bm * JXN * DN;

    if (tid < 32) {
        float v0 = g_rowmax[bm * JXN + tid];
        float v1 = g_rowmax[bm * JXN + tid + 32];
        float v2 = g_rowmax[bm * JXN + tid + 64];
        float v3 = g_rowmax[bm * JXN + tid + 96];
        float mx = fmaxf(fmaxf(v0, v1), fmaxf(v2, v3));
        #pragma unroll
        for (int o = 16; o >= 1; o >>= 1) mx = fmaxf(mx, __shfl_xor_sync(0xffffffffu, mx, o));
        float e0 = __expf(v0 - mx), e1 = __expf(v1 - mx);
        float e2 = __expf(v2 - mx), e3 = __expf(v3 - mx);
        float s = e0 + e1 + e2 + e3;
        #pragma unroll
        for (int o = 16; o >= 1; o >>= 1) s += __shfl_xor_sync(0xffffffffu, s, o);
        float inv = 1.f / s;
        p_s[tid]      = e0 * inv;
        p_s[tid + 32] = e1 * inv;
        p_s[tid + 64] = e2 * inv;
        p_s[tid + 96] = e3 * inv;
    }
    __syncthreads();

    const int jg = tid >> 6, dq = tid & 63;
    float4 acc = make_float4(0.f, 0.f, 0.f, 0.f);
    #pragma unroll 4
    for (int j = jg * 32; j < jg * 32 + 32; j++) {
        float4 hv = *(const float4*)(hb + j * DN + dq * 4);
        float pj = p_s[j];
        acc.x += pj * hv.x; acc.y += pj * hv.y; acc.z += pj * hv.z; acc.w += pj * hv.w;
    }
    part[jg][dq] = acc;
    __syncthreads();
    if (jg == 0) {
        float4 a0 = part[0][dq], a1 = part[1][dq], a2 = part[2][dq], a3 = part[3][dq];
        float4 ha;
        ha.x = a0.x + a1.x + a2.x + a3.x;
        ha.y = a0.y + a1.y + a2.y + a3.y;
        ha.z = a0.z + a1.z + a2.z + a3.z;
        ha.w = a0.w + a1.w + a2.w + a3.w;
        part[0][dq] = ha;
    }
    __syncthreads();
    const float4 ha = part[0][dq];
    #pragma unroll 2
    for (int j = jg * 32; j < jg * 32 + 32; j++) {
        float4 hv = *(const float4*)(hb + j * DN + dq * 4);   // L1-hot second read
        float4 o;
        o.x = hv.x * ha.x; o.y = hv.y * ha.y; o.z = hv.z * ha.z; o.w = hv.w * ha.w;
        *(float4*)(out + (size_t)(bm * JXN + j) * (4 * DN) + 3 * DN + dq * 4) = o;
    }
}

// ---------------------------------------------------------------------------
extern "C" void kernel_launch(void* const* d_in, const int* in_sizes, int n_in,
                              void* d_out, int out_size)
{
    (void)in_sizes; (void)n_in; (void)out_size;
    const float* h = (const float*)d_in[0];
    const float* u = (const float*)d_in[1];
    const float* w = (const float*)d_in[2];
    // d_in[3] is the scalar bias b: it cancels in both softmaxes -> unused.
    float* out = (float*)d_out;

    const size_t smem = SMEM_FLOATS * sizeof(float);  // 166,400 B
    cudaFuncSetAttribute(attn_k1, cudaFuncAttributeMaxDynamicSharedMemorySize, (int)smem);

    attn_k1<<<BB * MM * 2, 256, smem>>>(h, u, w, out);
    attn_k2<<<BB * MM, 256>>>(h, out);
}